// round 1
// baseline (speedup 1.0000x reference)
#include <cuda_runtime.h>
#include <cuda_bf16.h>

// Deformable conv2d, 1 channel, K=3, zero padding, torchvision bilinear rule.
// input : (B, 512, 512) f32
// weight: (1, 1, 3, 3)  f32
// offset: (B, 18, 512, 512) f32, layout [k*2+{y,x}][h][w]
// out   : (B, 512, 512) f32

#define HH 512
#define WW 512
#define HW (512 * 512)

__global__ __launch_bounds__(256) void DeformConv_90735479095316_kernel(
    const float* __restrict__ inp,
    const float* __restrict__ wgt,
    const float* __restrict__ off,
    float* __restrict__ out,
    int total)
{
    int idx = blockIdx.x * blockDim.x + threadIdx.x;
    if (idx >= total) return;

    int w = idx & (WW - 1);
    int h = (idx >> 9) & (HH - 1);
    int b = idx >> 18;

    const float* __restrict__ inb  = inp + b * HW;
    const float* __restrict__ offb = off + b * 18 * HW + (idx & (HW - 1));

    // Preload the 9 weights (uniform across threads; L1/const-cached).
    float wk[9];
    #pragma unroll
    for (int k = 0; k < 9; k++) wk[k] = __ldg(&wgt[k]);

    // Preload all 18 offsets up front for memory-level parallelism.
    float oy[9], ox[9];
    #pragma unroll
    for (int k = 0; k < 9; k++) {
        oy[k] = __ldg(&offb[(2 * k) * HW]);
        ox[k] = __ldg(&offb[(2 * k + 1) * HW]);
    }

    float acc = 0.0f;

    #pragma unroll
    for (int k = 0; k < 9; k++) {
        const int ky = (k / 3) - 1;
        const int kx = (k % 3) - 1;

        float y = (float)(h + ky) + oy[k];
        float x = (float)(w + kx) + ox[k];

        float y0f = floorf(y);
        float x0f = floorf(x);
        float ly = y - y0f;
        float lx = x - x0f;
        float hy = 1.0f - ly;
        float hx = 1.0f - lx;
        int y0 = (int)y0f;
        int x0 = (int)x0f;

        float v;
        if (y0 >= 0 && y0 < (HH - 1) && x0 >= 0 && x0 < (WW - 1)) {
            // Fast path: whole 2x2 footprint in-bounds. One base address,
            // 4 loads at immediate offsets.
            const float* __restrict__ p = inb + y0 * WW + x0;
            float v00 = __ldg(p);
            float v01 = __ldg(p + 1);
            float v10 = __ldg(p + WW);
            float v11 = __ldg(p + WW + 1);
            v = fmaf(hy, fmaf(hx, v00, lx * v01),
                     ly * fmaf(hx, v10, lx * v11));
        } else {
            // Slow path: per-corner zeroing, exactly as the reference.
            int y1 = y0 + 1;
            int x1 = x0 + 1;
            bool y0v = (y0 >= 0) && (y0 < HH);
            bool y1v = (y1 >= 0) && (y1 < HH);
            bool x0v = (x0 >= 0) && (x0 < WW);
            bool x1v = (x1 >= 0) && (x1 < WW);
            float v00 = (y0v && x0v) ? __ldg(&inb[y0 * WW + x0]) : 0.0f;
            float v01 = (y0v && x1v) ? __ldg(&inb[y0 * WW + x1]) : 0.0f;
            float v10 = (y1v && x0v) ? __ldg(&inb[y1 * WW + x0]) : 0.0f;
            float v11 = (y1v && x1v) ? __ldg(&inb[y1 * WW + x1]) : 0.0f;
            v = fmaf(hy, fmaf(hx, v00, lx * v01),
                     ly * fmaf(hx, v10, lx * v11));
        }

        acc = fmaf(wk[k], v, acc);
    }

    out[idx] = acc;
}

extern "C" void kernel_launch(void* const* d_in, const int* in_sizes, int n_in,
                              void* d_out, int out_size)
{
    const float* inp = (const float*)d_in[0];
    const float* wgt = (const float*)d_in[1];
    const float* off = (const float*)d_in[2];
    float* out = (float*)d_out;

    int total = out_size;  // B * H * W
    int threads = 256;
    int blocks = (total + threads - 1) / threads;
    DeformConv_90735479095316_kernel<<<blocks, threads>>>(inp, wgt, off, out, total);
}